// round 13
// baseline (speedup 1.0000x reference)
#include <cuda_runtime.h>
#include <cuda_bf16.h>

#define NB 4096
#define FULLMASK 0xFFFFFFFFu

// ---------------- device-global state (zero-init at load; re-zeroed by last block each run) ----------------
__device__ unsigned int       g_cnt[NB];   // per-bin counts
__device__ unsigned long long g_msum[NB];  // per-bin sum of low-20 mantissa bits
__device__ unsigned int       g_done;      // last-block-done counter

// fast relative error: ~2-3 ulp from __fdividef; self-consistent (same value binned and summed)
__device__ __forceinline__ float rel_err(float o, float t) {
    float r = __fdividef(t - o, t);
    return r * r;
}

// warp-aggregated packed atomic: lanes sharing a bin combine; leader issues ONE atomic.
// Requires all 32 lanes active (caller guarantees warp-uniform control flow).
__device__ __forceinline__ void agg_add(unsigned long long* __restrict__ sh,
                                        unsigned int key, int lane) {
    unsigned int bin = key >> 20;
    unsigned int m   = key & 0xFFFFFu;
    unsigned int mask = __match_any_sync(FULLMASK, bin);
    unsigned int tot  = __reduce_add_sync(mask, m);     // <= 32 * 2^20 < 2^25, fits u32
    if (lane == (int)(__ffs(mask) - 1)) {
        unsigned long long add =
            ((unsigned long long)__popc(mask) << 48) | (unsigned long long)tot;
        atomicAdd(&sh[bin], add);
    }
}

// ---------------- single fused kernel: histogram+sums, then last block finalizes ----------------
// key = float bits of err (>= 0). bin = key>>20. m = key & 0xFFFFF.
// err == v_lo(bin) + 2^exp(bin) * m * 2^-23 EXACTLY, so per-bin (count, sum_m) give exact bin sums.
__global__ __launch_bounds__(512) void k_all(const float* __restrict__ out,
                                             const float* __restrict__ tgt,
                                             int n, float* __restrict__ result) {
    __shared__ unsigned long long sh[NB];   // 32 KB: (count<<48) | sum_m
    for (int i = threadIdx.x; i < NB; i += blockDim.x) sh[i] = 0ull;
    __syncthreads();

    const int lane = threadIdx.x & 31;
    const int n4 = n >> 2;
    const float4* __restrict__ o4 = (const float4*)out;
    const float4* __restrict__ t4 = (const float4*)tgt;
    const int stride = gridDim.x * blockDim.x;

    int i  = blockIdx.x * blockDim.x + threadIdx.x;
    int iw = i - lane;                      // warp-base index: uniform loop bounds

    // main loop, unrolled x2, warp-uniform trip count (all 32 lanes active -> FULLMASK legal)
    while (iw + stride + 31 < n4) {
        float4 oa = o4[i];
        float4 ta = t4[i];
        float4 ob = o4[i + stride];
        float4 tb = t4[i + stride];
        agg_add(sh, __float_as_uint(rel_err(oa.x, ta.x)), lane);
        agg_add(sh, __float_as_uint(rel_err(oa.y, ta.y)), lane);
        agg_add(sh, __float_as_uint(rel_err(oa.z, ta.z)), lane);
        agg_add(sh, __float_as_uint(rel_err(oa.w, ta.w)), lane);
        agg_add(sh, __float_as_uint(rel_err(ob.x, tb.x)), lane);
        agg_add(sh, __float_as_uint(rel_err(ob.y, tb.y)), lane);
        agg_add(sh, __float_as_uint(rel_err(ob.z, tb.z)), lane);
        agg_add(sh, __float_as_uint(rel_err(ob.w, tb.w)), lane);
        i  += 2 * stride;
        iw += 2 * stride;
    }
    // single-step, still warp-uniform
    while (iw + 31 < n4) {
        float4 o = o4[i];
        float4 t = t4[i];
        agg_add(sh, __float_as_uint(rel_err(o.x, t.x)), lane);
        agg_add(sh, __float_as_uint(rel_err(o.y, t.y)), lane);
        agg_add(sh, __float_as_uint(rel_err(o.z, t.z)), lane);
        agg_add(sh, __float_as_uint(rel_err(o.w, t.w)), lane);
        i  += stride;
        iw += stride;
    }
    // straddling partial warp (<32 float4 grid-wide): plain atomics
    if (i < n4) {
        float4 o = o4[i];
        float4 t = t4[i];
        unsigned int key[4];
        key[0] = __float_as_uint(rel_err(o.x, t.x));
        key[1] = __float_as_uint(rel_err(o.y, t.y));
        key[2] = __float_as_uint(rel_err(o.z, t.z));
        key[3] = __float_as_uint(rel_err(o.w, t.w));
#pragma unroll
        for (int j = 0; j < 4; j++)
            atomicAdd(&sh[key[j] >> 20],
                      (1ull << 48) | (unsigned long long)(key[j] & 0xFFFFFu));
    }
    // scalar tail (n not multiple of 4)
    int tail_base = n4 << 2;
    int gtid = blockIdx.x * blockDim.x + threadIdx.x;
    if (tail_base + gtid < n) {
        unsigned int key = __float_as_uint(rel_err(out[tail_base + gtid], tgt[tail_base + gtid]));
        atomicAdd(&sh[key >> 20], (1ull << 48) | (unsigned long long)(key & 0xFFFFFu));
    }
    __syncthreads();

    // flush to global
    for (int b = threadIdx.x; b < NB; b += blockDim.x) {
        unsigned long long v = sh[b];
        if (v) {
            atomicAdd(&g_cnt[b], (unsigned int)(v >> 48));
            atomicAdd(&g_msum[b], v & 0xFFFFFFFFFFFFull);
        }
    }

    // ---- last-block-done gate ----
    __shared__ unsigned int s_islast;
    __threadfence();
    if (threadIdx.x == 0) {
        unsigned int v = atomicAdd(&g_done, 1u);
        s_islast = (v == gridDim.x - 1) ? 1u : 0u;
    }
    __syncthreads();
    if (!s_islast) return;

    // ================= finalize (last block, 512 threads) =================
    __shared__ unsigned long long s_warp[16];
    __shared__ double dsum[16];
    __shared__ unsigned int sB;
    __shared__ unsigned long long sBelow;

    int t = threadIdx.x;
    int wid = t >> 5;
    long long k = (long long)((double)n * 0.97);   // matches python int(N*0.97)

    // 8 bins per thread; read via __ldcg (bypass L1; data written by other blocks' atomics)
    uint4 va = __ldcg(((const uint4*)g_cnt) + 2 * t);
    uint4 vb = __ldcg(((const uint4*)g_cnt) + 2 * t + 1);
    unsigned int raw[8] = {va.x, va.y, va.z, va.w, vb.x, vb.y, vb.z, vb.w};
    unsigned long long thread_tot = 0;
#pragma unroll
    for (int j = 0; j < 8; j++) thread_tot += raw[j];

    // warp inclusive scan of thread totals
    unsigned long long s = thread_tot;
#pragma unroll
    for (int off = 1; off < 32; off <<= 1) {
        unsigned long long u = __shfl_up_sync(FULLMASK, s, off);
        if (lane >= off) s += u;
    }
    if (lane == 31) s_warp[wid] = s;
    __syncthreads();
    if (wid == 0 && lane < 16) {
        unsigned long long w = s_warp[lane];
        unsigned long long ws = w;
#pragma unroll
        for (int off = 1; off < 16; off <<= 1) {
            unsigned long long u = __shfl_up_sync(0xFFFFu, ws, off);
            if (lane >= off) ws += u;
        }
        s_warp[lane] = ws - w;   // exclusive prefix of warp sums
    }
    __syncthreads();

    unsigned long long run = s_warp[wid] + (s - thread_tot);  // exclusive prefix for this thread
#pragma unroll
    for (int j = 0; j < 8; j++) {
        unsigned long long exc = run;
        run += raw[j];
        if ((long long)exc < k && (long long)run >= k) {
            sB = (unsigned int)(t * 8 + j);
            sBelow = exc;
        }
    }
    __syncthreads();

    unsigned int B = sB;
    long long cbelow = (long long)sBelow;

    // exact sum over bins strictly below B:
    // bin b: v_lo = float(b<<20), p2 = 2^exp = float((b>>3)<<23); sum = c*v_lo + p2*msum*2^-23
    double part = 0.0;
    for (int b = t; b < (int)B; b += blockDim.x) {
        unsigned int c = __ldcg(&g_cnt[b]);
        if (c) {
            double vlo = (double)__uint_as_float((unsigned int)b << 20);
            double p2  = (double)__uint_as_float((unsigned int)(b >> 3) << 23);
            part += (double)c * vlo + p2 * (double)__ldcg(&g_msum[b]) * (1.0 / 8388608.0);
        }
    }
#pragma unroll
    for (int off = 16; off >= 1; off >>= 1)
        part += __shfl_down_sync(FULLMASK, part, off);
    if (lane == 0) dsum[wid] = part;
    __syncthreads();

    if (t == 0) {
        double sum_below = 0.0;
        for (int w = 0; w < 16; w++) sum_below += dsum[w];

        // boundary bin: take r smallest of c; calibrated interpolation msum_partial ~= msum*(r/c)^2
        long long r = k - cbelow;             // 1..c
        unsigned int c = __ldcg(&g_cnt[B]);
        unsigned long long Sm = __ldcg(&g_msum[B]);
        double vlo = (double)__uint_as_float(B << 20);
        double p2  = (double)__uint_as_float((unsigned int)(B >> 3) << 23);
        double frac = (double)r / (double)c;
        double partial = (double)r * vlo + p2 * (double)Sm * frac * frac * (1.0 / 8388608.0);

        result[0] = (float)((sum_below + partial) / (double)k);
    }
    __syncthreads();

    // re-zero state for next run / graph replay (deterministic across calls)
    for (int b = t; b < NB; b += blockDim.x) {
        g_cnt[b]  = 0u;
        g_msum[b] = 0ull;
    }
    if (t == 0) g_done = 0u;
}

// ---------------- launch: ONE kernel ----------------
extern "C" void kernel_launch(void* const* d_in, const int* in_sizes, int n_in,
                              void* d_out, int out_size) {
    const float* output = (const float*)d_in[0];
    const float* target = (const float*)d_in[1];
    int n = in_sizes[0];
    if (n <= 0) return;

    k_all<<<592, 512>>>(output, target, n, (float*)d_out);
}

// round 14
// speedup vs baseline: 9.9400x; 9.9400x over previous
#include <cuda_runtime.h>
#include <cuda_bf16.h>

#define NB 4096
#define FULLMASK 0xFFFFFFFFu
#define SPT 2              // float4 samples per thread (sample kernel)
#define MARGIN 0.0025      // ~8 sigma for ~300K samples

// ---------------- device-global state (zero-init; each kernel's last block re-zeros its own) ----------------
__device__ unsigned int       g_shist[NB];     // sample histogram
__device__ unsigned int       g_done1;
__device__ unsigned int       g_loKey, g_hiKey, g_shift;

__device__ unsigned int       g_cnt2[NB];      // bracket sub-bin counts
__device__ double             g_fsum2[NB];     // bracket sub-bin value sums
__device__ unsigned long long g_below_cnt;
__device__ double             g_below_sum;
__device__ unsigned int       g_done2;

__device__ __forceinline__ float rel_err(float o, float t) {
    float r = __fdividef(t - o, t);
    return r * r;
}

// ================= K1: sampled histogram + bracket selection =================
__global__ __launch_bounds__(256) void k_sample(const float* __restrict__ out,
                                                const float* __restrict__ tgt,
                                                int n) {
    __shared__ unsigned int sh[NB];
    for (int i = threadIdx.x; i < NB; i += 256) sh[i] = 0u;
    __syncthreads();

    int n4 = n >> 2;
    int nthreads = gridDim.x * 256;
    int tid = blockIdx.x * 256 + threadIdx.x;
    int stride4 = n4 / (nthreads * SPT);
    if (stride4 < 1) stride4 = 1;

    const float4* __restrict__ o4 = (const float4*)out;
    const float4* __restrict__ t4 = (const float4*)tgt;
#pragma unroll
    for (int s = 0; s < SPT; s++) {
        long long idx = (long long)(tid + s * nthreads) * stride4;
        if (idx < n4) {
            float4 o = o4[idx];
            float4 t = t4[idx];
            atomicAdd(&sh[__float_as_uint(rel_err(o.x, t.x)) >> 20], 1u);
            atomicAdd(&sh[__float_as_uint(rel_err(o.y, t.y)) >> 20], 1u);
            atomicAdd(&sh[__float_as_uint(rel_err(o.z, t.z)) >> 20], 1u);
            atomicAdd(&sh[__float_as_uint(rel_err(o.w, t.w)) >> 20], 1u);
        }
    }
    __syncthreads();
    for (int b = threadIdx.x; b < NB; b += 256)
        if (sh[b]) atomicAdd(&g_shist[b], sh[b]);

    __shared__ unsigned int s_islast;
    __threadfence();
    if (threadIdx.x == 0)
        s_islast = (atomicAdd(&g_done1, 1u) == gridDim.x - 1) ? 1u : 0u;
    __syncthreads();
    if (!s_islast) return;

    // ---- bracket selection: 256 threads x 16 bins ----
    __shared__ unsigned long long sw[8];
    __shared__ unsigned long long sTS;
    __shared__ unsigned int sLo, sHi;

    int t = threadIdx.x, lane = t & 31, wid = t >> 5;
    unsigned int raw[16];
    unsigned long long ttot = 0;
#pragma unroll
    for (int j = 0; j < 16; j++) { raw[j] = __ldcg(&g_shist[t * 16 + j]); ttot += raw[j]; }

    unsigned long long s = ttot;
#pragma unroll
    for (int off = 1; off < 32; off <<= 1) {
        unsigned long long u = __shfl_up_sync(FULLMASK, s, off);
        if (lane >= off) s += u;
    }
    if (lane == 31) sw[wid] = s;
    __syncthreads();
    if (wid == 0 && lane < 8) {
        unsigned long long w = sw[lane];
        unsigned long long ws = w;
#pragma unroll
        for (int off = 1; off < 8; off <<= 1) {
            unsigned long long u = __shfl_up_sync(0xFFu, ws, off);
            if (lane >= off) ws += u;
        }
        sw[lane] = ws - w;      // exclusive prefix of warp sums
    }
    __syncthreads();
    unsigned long long base = sw[wid] + (s - ttot);
    if (t == 255) sTS = base + ttot;
    __syncthreads();

    unsigned long long TS = sTS;
    long long wlo = (long long)((0.97 - MARGIN) * (double)TS); if (wlo < 1) wlo = 1;
    long long whi = (long long)((0.97 + MARGIN) * (double)TS) + 1;
    if (whi > (long long)TS) whi = (long long)TS;
    if (whi < wlo) whi = wlo;

    unsigned long long run = base;
#pragma unroll
    for (int j = 0; j < 16; j++) {
        unsigned long long exc = run;
        run += raw[j];
        if ((long long)exc < wlo && (long long)run >= wlo) sLo = (unsigned int)(t * 16 + j);
        if ((long long)exc < whi && (long long)run >= whi) sHi = (unsigned int)(t * 16 + j);
    }
    __syncthreads();

    if (t == 0) {
        unsigned int lo = sLo, hi = sHi;
        if (hi < lo) hi = lo;
        unsigned int loKey = lo << 20;
        unsigned int hiKey = (hi + 1) << 20;
        unsigned int span = hiKey - loKey;
        unsigned int shift = 8;
        while ((span >> shift) > NB) shift++;
        g_loKey = loKey; g_hiKey = hiKey; g_shift = shift;
        g_done1 = 0u;
    }
    // re-zero sample hist for next graph replay
    for (int j = 0; j < 16; j++) g_shist[t * 16 + j] = 0u;
}

// ================= K2: single full pass + last-block finalize =================
__global__ __launch_bounds__(512, 4) void k_main(const float* __restrict__ out,
                                                 const float* __restrict__ tgt,
                                                 int n, float* __restrict__ result) {
    __shared__ unsigned int cnt2[NB];
    __shared__ float fs2[NB];
    __shared__ double wsum[16];
    __shared__ unsigned int wcnt[16];
    for (int i = threadIdx.x; i < NB; i += blockDim.x) { cnt2[i] = 0u; fs2[i] = 0.0f; }
    __syncthreads();

    const unsigned int loKey = g_loKey;
    const unsigned int hiKey = g_hiKey;
    const unsigned int shift = g_shift;

    float a0 = 0.f, a1 = 0.f, a2 = 0.f, a3 = 0.f;
    unsigned int my_below = 0;

    int n4 = n >> 2;
    const float4* __restrict__ o4 = (const float4*)out;
    const float4* __restrict__ t4 = (const float4*)tgt;
    int stride = gridDim.x * blockDim.x;
    int i = blockIdx.x * blockDim.x + threadIdx.x;

    for (; i + stride < n4; i += 2 * stride) {
        float4 oa = o4[i];
        float4 ta = t4[i];
        float4 ob = o4[i + stride];
        float4 tb = t4[i + stride];
        float e[8];
        e[0] = rel_err(oa.x, ta.x); e[1] = rel_err(oa.y, ta.y);
        e[2] = rel_err(oa.z, ta.z); e[3] = rel_err(oa.w, ta.w);
        e[4] = rel_err(ob.x, tb.x); e[5] = rel_err(ob.y, tb.y);
        e[6] = rel_err(ob.z, tb.z); e[7] = rel_err(ob.w, tb.w);
#pragma unroll
        for (int j = 0; j < 8; j++) {
            unsigned int key = __float_as_uint(e[j]);
            if (key < loKey) {
                my_below++;
                if ((j & 3) == 0) a0 += e[j];
                else if ((j & 3) == 1) a1 += e[j];
                else if ((j & 3) == 2) a2 += e[j];
                else a3 += e[j];
            } else if (key < hiKey) {
                unsigned int idx = (key - loKey) >> shift;
                atomicAdd(&cnt2[idx], 1u);
                atomicAdd(&fs2[idx], e[j]);
            }
        }
    }
    for (; i < n4; i += stride) {
        float4 o = o4[i];
        float4 t = t4[i];
        float e[4];
        e[0] = rel_err(o.x, t.x); e[1] = rel_err(o.y, t.y);
        e[2] = rel_err(o.z, t.z); e[3] = rel_err(o.w, t.w);
#pragma unroll
        for (int j = 0; j < 4; j++) {
            unsigned int key = __float_as_uint(e[j]);
            if (key < loKey) {
                my_below++;
                if (j == 0) a0 += e[j];
                else if (j == 1) a1 += e[j];
                else if (j == 2) a2 += e[j];
                else a3 += e[j];
            } else if (key < hiKey) {
                unsigned int idx = (key - loKey) >> shift;
                atomicAdd(&cnt2[idx], 1u);
                atomicAdd(&fs2[idx], e[j]);
            }
        }
    }
    int tail_base = n4 << 2;
    int gtid = blockIdx.x * blockDim.x + threadIdx.x;
    if (tail_base + gtid < n) {
        float e = rel_err(out[tail_base + gtid], tgt[tail_base + gtid]);
        unsigned int key = __float_as_uint(e);
        if (key < loKey) { my_below++; a0 += e; }
        else if (key < hiKey) {
            unsigned int idx = (key - loKey) >> shift;
            atomicAdd(&cnt2[idx], 1u);
            atomicAdd(&fs2[idx], e);
        }
    }

    // block reduce below-count and below-sum -> one global atomic each
    double acc = ((double)a0 + (double)a1) + ((double)a2 + (double)a3);
    int lane = threadIdx.x & 31;
    int wid = threadIdx.x >> 5;
#pragma unroll
    for (int off = 16; off >= 1; off >>= 1) {
        acc += __shfl_down_sync(FULLMASK, acc, off);
        my_below += __shfl_down_sync(FULLMASK, my_below, off);
    }
    if (lane == 0) { wsum[wid] = acc; wcnt[wid] = my_below; }
    __syncthreads();
    if (threadIdx.x == 0) {
        double sdsum = 0.0;
        unsigned long long scnt = 0;
        for (int w = 0; w < 16; w++) { sdsum += wsum[w]; scnt += wcnt[w]; }
        atomicAdd(&g_below_sum, sdsum);
        atomicAdd(&g_below_cnt, scnt);
    }

    // flush bracket sub-bins
    for (int b = threadIdx.x; b < NB; b += blockDim.x) {
        unsigned int c = cnt2[b];
        if (c) {
            atomicAdd(&g_cnt2[b], c);
            atomicAdd(&g_fsum2[b], (double)fs2[b]);
        }
    }

    // ---- last-block gate ----
    __shared__ unsigned int s_islast;
    __threadfence();
    if (threadIdx.x == 0)
        s_islast = (atomicAdd(&g_done2, 1u) == gridDim.x - 1) ? 1u : 0u;
    __syncthreads();
    if (!s_islast) return;

    // ================= finalize (512 threads, 8 sub-bins each) =================
    __shared__ unsigned long long s_warp[16];
    __shared__ double dsum[16];
    __shared__ unsigned int sB;
    __shared__ unsigned long long sBelow;

    int t = threadIdx.x;
    long long k = (long long)((double)n * 0.97);   // matches python int(N*0.97)
    unsigned long long below = 0;
    { // read via atomic for coherence
        if (t == 0) sBelow = atomicAdd(&g_below_cnt, 0ull);
        __syncthreads();
        below = sBelow;
    }
    long long want = k - (long long)below;   // crossing inside bracket (guaranteed by margins)

    uint4 va = __ldcg(((const uint4*)g_cnt2) + 2 * t);
    uint4 vb = __ldcg(((const uint4*)g_cnt2) + 2 * t + 1);
    unsigned int raw[8] = {va.x, va.y, va.z, va.w, vb.x, vb.y, vb.z, vb.w};
    unsigned long long ttot = 0;
#pragma unroll
    for (int j = 0; j < 8; j++) ttot += raw[j];

    unsigned long long s = ttot;
#pragma unroll
    for (int off = 1; off < 32; off <<= 1) {
        unsigned long long u = __shfl_up_sync(FULLMASK, s, off);
        if (lane >= off) s += u;
    }
    if (lane == 31) s_warp[wid] = s;
    __syncthreads();
    if (wid == 0 && lane < 16) {
        unsigned long long w = s_warp[lane];
        unsigned long long ws = w;
#pragma unroll
        for (int off = 1; off < 16; off <<= 1) {
            unsigned long long u = __shfl_up_sync(0xFFFFu, ws, off);
            if (lane >= off) ws += u;
        }
        s_warp[lane] = ws - w;
    }
    __syncthreads();

    unsigned long long run = s_warp[wid] + (s - ttot);
#pragma unroll
    for (int j = 0; j < 8; j++) {
        unsigned long long exc = run;
        run += raw[j];
        if ((long long)exc < want && (long long)run >= want) {
            sB = (unsigned int)(t * 8 + j);
            sBelow = exc;      // reuse: sub-bin exclusive count
        }
    }
    __syncthreads();

    unsigned int S = sB;
    long long cbelow2 = (long long)sBelow;

    // parallel sum of bracket sums for sub-bins < S
    double part = 0.0;
    for (int b = t; b < (int)S; b += blockDim.x) part += __ldcg(&g_fsum2[b]);
#pragma unroll
    for (int off = 16; off >= 1; off >>= 1)
        part += __shfl_down_sync(FULLMASK, part, off);
    if (lane == 0) dsum[wid] = part;
    __syncthreads();

    if (t == 0) {
        double sum2 = 0.0;
        for (int w = 0; w < 16; w++) sum2 += dsum[w];

        long long r = want - cbelow2;                  // 1..c
        unsigned int c = __ldcg(&g_cnt2[S]);
        double fs = __ldcg(&g_fsum2[S]);
        double a = (double)__uint_as_float(g_loKey + (S << g_shift));  // sub-bin low edge
        double mean = fs / (double)c;
        // sum of r smallest of c, linear-cdf model: r*(a + (mean-a)*(r/c)); exact at r==c
        double partial = (double)r * (a + (mean - a) * ((double)r / (double)c));

        double total = atomicAdd(&g_below_sum, 0.0) + sum2 + partial;
        result[0] = (float)(total / (double)k);
    }
    __syncthreads();

    // re-zero state for next graph replay
    for (int b = t; b < NB; b += blockDim.x) { g_cnt2[b] = 0u; g_fsum2[b] = 0.0; }
    if (t == 0) {
        g_below_cnt = 0ull;
        g_below_sum = 0.0;
        g_done2 = 0u;
    }
}

// ---------------- launch: two kernels ----------------
extern "C" void kernel_launch(void* const* d_in, const int* in_sizes, int n_in,
                              void* d_out, int out_size) {
    const float* output = (const float*)d_in[0];
    const float* target = (const float*)d_in[1];
    int n = in_sizes[0];
    if (n <= 0) return;

    k_sample<<<148, 256>>>(output, target, n);
    k_main<<<592, 512>>>(output, target, n, (float*)d_out);
}